// round 3
// baseline (speedup 1.0000x reference)
#include <cuda_runtime.h>
#include <cuda_bf16.h>

#define NN 100000     // nodes
#define NE 1600000    // edges
#define NG 2048       // graphs
#define NFD 64        // node feature dim
#define DD 32         // hidden dim
#define BN_EPS 1e-5f

// ---------------- scratch (static __device__, no allocation) ----------------
__device__ float  g_agg[NN * NFD];        // layer1 uses NF=64, later layers use first N*32
__device__ float  g_t[NN * DD];           // MLP output (pre-BN) per layer
__device__ double g_stats[2 * DD];        // sum | sumsq per feature
__device__ float  g_scale[DD];            // folded BN scale
__device__ float  g_shift[DD];            // folded BN shift
__device__ float  g_pooled[NG * DD];
__device__ float  g_s1[NG * 256];
__device__ float  g_z[NG * 256];          // [gfeat(128) | s2(128)]
__device__ float  g_z1[NG * 1024];
__device__ float  g_z2[NG * 256];

// ---------------- layer 1 ----------------
__global__ void k_agg1_init(const float* __restrict__ x) {
    int idx = blockIdx.x * blockDim.x + threadIdx.x;
    if (idx < NN * NFD) g_agg[idx] = x[idx];
    if (idx < 2 * DD)   g_stats[idx] = 0.0;
}

// warp handles (edge, half-of-64-features)  -- edge_index is int32!
__global__ void k_agg1_edges(const float* __restrict__ x, const int* __restrict__ ei) {
    int t = blockIdx.x * blockDim.x + threadIdx.x;
    int w = t >> 5;
    if (w >= NE * 2) return;
    int e = w >> 1;
    int f = ((w & 1) << 5) | (t & 31);
    int s = ei[e];
    int d = ei[NE + e];
    atomicAdd(&g_agg[(long)d * NFD + f], x[(long)s * NFD + f]);
}

// per-row MLP: relu(agg@wa + ba) @ wb + bb, 64->32->32, fused BN-stat accumulation
__global__ void k_mlp1(const float* __restrict__ wa, const float* __restrict__ ba,
                       const float* __restrict__ wb, const float* __restrict__ bb) {
    __shared__ float swa[NFD * DD];
    __shared__ float swb[DD * DD];
    __shared__ float sba[DD], sbb[DD];
    int tid = threadIdx.x;
    for (int i = tid; i < NFD * DD; i += blockDim.x) swa[i] = wa[i];
    for (int i = tid; i < DD * DD; i += blockDim.x)  swb[i] = wb[i];
    if (tid < DD) { sba[tid] = ba[tid]; sbb[tid] = bb[tid]; }
    __syncthreads();

    int lane   = tid & 31;
    int warp   = (blockIdx.x * blockDim.x + tid) >> 5;
    int nwarps = (gridDim.x * blockDim.x) >> 5;
    float ssum = 0.f, ssq = 0.f;
    for (int r = warp; r < NN; r += nwarps) {
        float a0 = g_agg[r * NFD + lane];
        float a1 = g_agg[r * NFD + 32 + lane];
        float h = sba[lane];
        #pragma unroll
        for (int k = 0; k < 32; k++)
            h = fmaf(__shfl_sync(0xffffffffu, a0, k), swa[k * DD + lane], h);
        #pragma unroll
        for (int k = 0; k < 32; k++)
            h = fmaf(__shfl_sync(0xffffffffu, a1, k), swa[(k + 32) * DD + lane], h);
        h = fmaxf(h, 0.f);
        float o = sbb[lane];
        #pragma unroll
        for (int k = 0; k < 32; k++)
            o = fmaf(__shfl_sync(0xffffffffu, h, k), swb[k * DD + lane], o);
        g_t[r * DD + lane] = o;
        ssum += o;
        ssq  = fmaf(o, o, ssq);
    }
    atomicAdd(&g_stats[lane], (double)ssum);
    atomicAdd(&g_stats[DD + lane], (double)ssq);
}

// ---------------- layers 2-5 ----------------
__global__ void k_bnfin(const float* __restrict__ g, const float* __restrict__ b) {
    int f = threadIdx.x;
    if (f >= DD) return;
    double mu  = g_stats[f] / (double)NN;
    double var = g_stats[DD + f] / (double)NN - mu * mu;
    float sc = g[f] * rsqrtf((float)var + BN_EPS);
    g_scale[f] = sc;
    g_shift[f] = b[f] - (float)mu * sc;
}

__global__ void k_agg_init() {
    int idx = blockIdx.x * blockDim.x + threadIdx.x;
    if (idx < NN * DD) {
        int f = idx & 31;
        g_agg[idx] = fmaxf(fmaf(g_t[idx], g_scale[f], g_shift[f]), 0.f);
    }
    if (idx < 2 * DD) g_stats[idx] = 0.0;
}

__global__ void k_agg_edges(const int* __restrict__ ei) {
    int t = blockIdx.x * blockDim.x + threadIdx.x;
    int e = t >> 5;
    if (e >= NE) return;
    int f = t & 31;
    int s = ei[e];
    int d = ei[NE + e];
    float v = fmaxf(fmaf(g_t[(long)s * DD + f], g_scale[f], g_shift[f]), 0.f);
    atomicAdd(&g_agg[(long)d * DD + f], v);
}

__global__ void k_mlp(const float* __restrict__ wa, const float* __restrict__ ba,
                      const float* __restrict__ wb, const float* __restrict__ bb) {
    __shared__ float swa[DD * DD];
    __shared__ float swb[DD * DD];
    __shared__ float sba[DD], sbb[DD];
    int tid = threadIdx.x;
    for (int i = tid; i < DD * DD; i += blockDim.x) { swa[i] = wa[i]; swb[i] = wb[i]; }
    if (tid < DD) { sba[tid] = ba[tid]; sbb[tid] = bb[tid]; }
    __syncthreads();

    int lane   = tid & 31;
    int warp   = (blockIdx.x * blockDim.x + tid) >> 5;
    int nwarps = (gridDim.x * blockDim.x) >> 5;
    float ssum = 0.f, ssq = 0.f;
    for (int r = warp; r < NN; r += nwarps) {
        float a = g_agg[r * DD + lane];
        float h = sba[lane];
        #pragma unroll
        for (int k = 0; k < 32; k++)
            h = fmaf(__shfl_sync(0xffffffffu, a, k), swa[k * DD + lane], h);
        h = fmaxf(h, 0.f);
        float o = sbb[lane];
        #pragma unroll
        for (int k = 0; k < 32; k++)
            o = fmaf(__shfl_sync(0xffffffffu, h, k), swb[k * DD + lane], o);
        g_t[r * DD + lane] = o;
        ssum += o;
        ssq  = fmaf(o, o, ssq);
    }
    atomicAdd(&g_stats[lane], (double)ssum);
    atomicAdd(&g_stats[DD + lane], (double)ssq);
}

// ---------------- pooling ----------------
__global__ void k_pool_zero() {
    int idx = blockIdx.x * blockDim.x + threadIdx.x;
    if (idx < NG * DD) g_pooled[idx] = 0.f;
}

__global__ void k_pool(const int* __restrict__ batch) {
    int idx = blockIdx.x * blockDim.x + threadIdx.x;
    if (idx >= NN * DD) return;
    int i = idx >> 5, f = idx & 31;
    float v = fmaxf(fmaf(g_t[idx], g_scale[f], g_shift[f]), 0.f);
    atomicAdd(&g_pooled[batch[i] * DD + f], v);
}

// ---------------- head GEMM: C = relu?(A[M,K] @ W[K,Nc] + bias), C has ldc ----------------
__global__ void k_gemm(const float* __restrict__ A, const float* __restrict__ W,
                       const float* __restrict__ bias, float* __restrict__ C,
                       int M, int K, int Nc, int ldc, int do_relu) {
    const int BM = 64, BN = 64, BK = 16;
    __shared__ float As[BK][BM + 1];
    __shared__ float Ws[BK][BN];
    int tx = threadIdx.x & 15, ty = threadIdx.x >> 4;
    int row0 = blockIdx.y * BM, col0 = blockIdx.x * BN;
    float acc[4][4] = {};
    for (int k0 = 0; k0 < K; k0 += BK) {
        for (int i = threadIdx.x; i < BM * BK; i += 256) {
            int m = i >> 4, kk = i & 15;
            As[kk][m] = A[(long)(row0 + m) * K + k0 + kk];
        }
        for (int i = threadIdx.x; i < BK * BN; i += 256) {
            int kk = i >> 6, n = i & 63;
            Ws[kk][n] = W[(long)(k0 + kk) * Nc + col0 + n];
        }
        __syncthreads();
        #pragma unroll
        for (int kk = 0; kk < BK; kk++) {
            float a[4], w[4];
            #pragma unroll
            for (int i = 0; i < 4; i++) a[i] = As[kk][ty * 4 + i];
            #pragma unroll
            for (int j = 0; j < 4; j++) w[j] = Ws[kk][tx * 4 + j];
            #pragma unroll
            for (int i = 0; i < 4; i++)
                #pragma unroll
                for (int j = 0; j < 4; j++) acc[i][j] = fmaf(a[i], w[j], acc[i][j]);
        }
        __syncthreads();
    }
    #pragma unroll
    for (int i = 0; i < 4; i++) {
        int r = row0 + ty * 4 + i;
        #pragma unroll
        for (int j = 0; j < 4; j++) {
            int c = col0 + tx * 4 + j;
            float v = acc[i][j] + bias[c];
            if (do_relu) v = fmaxf(v, 0.f);
            C[(long)r * ldc + c] = v;
        }
    }
}

// final matvec: out[g] = z2[g,:] @ out_w + out_b
__global__ void k_out(const float* __restrict__ ow, const float* __restrict__ ob,
                      float* __restrict__ out) {
    int warp = (blockIdx.x * blockDim.x + threadIdx.x) >> 5;
    int lane = threadIdx.x & 31;
    if (warp >= NG) return;
    float acc = 0.f;
    #pragma unroll
    for (int k = lane; k < 256; k += 32)
        acc = fmaf(g_z2[warp * 256 + k], ow[k], acc);
    #pragma unroll
    for (int o = 16; o; o >>= 1) acc += __shfl_down_sync(0xffffffffu, acc, o);
    if (lane == 0) out[warp] = acc + ob[0];
}

// ---------------- launch ----------------
extern "C" void kernel_launch(void* const* d_in, const int* in_sizes, int n_in,
                              void* d_out, int out_size) {
    const float* x     = (const float*)d_in[0];
    const int*   ei    = (const int*)d_in[1];     // int32! (JAX x64 disabled)
    const int*   batch = (const int*)d_in[2];     // int32!
    const float* sf    = (const float*)d_in[3];
    const float* w1a   = (const float*)d_in[4];
    const float* b1a   = (const float*)d_in[5];
    const float* ws_a  = (const float*)d_in[6];
    const float* bs_a  = (const float*)d_in[7];
    const float* ws_b  = (const float*)d_in[8];
    const float* bs_b  = (const float*)d_in[9];
    const float* bn_g  = (const float*)d_in[10];
    const float* bn_b  = (const float*)d_in[11];
    const float* fcg_w = (const float*)d_in[12];
    const float* fcg_b = (const float*)d_in[13];
    const float* fs1_w = (const float*)d_in[14];
    const float* fs1_b = (const float*)d_in[15];
    const float* fs2_w = (const float*)d_in[16];
    const float* fs2_b = (const float*)d_in[17];
    const float* fc1_w = (const float*)d_in[18];
    const float* fc1_b = (const float*)d_in[19];
    const float* fc2_w = (const float*)d_in[20];
    const float* fc2_b = (const float*)d_in[21];
    const float* out_w = (const float*)d_in[22];
    const float* out_b = (const float*)d_in[23];
    float* out = (float*)d_out;

    float *p_pooled, *p_s1, *p_z, *p_z1, *p_z2;
    cudaGetSymbolAddress((void**)&p_pooled, g_pooled);
    cudaGetSymbolAddress((void**)&p_s1, g_s1);
    cudaGetSymbolAddress((void**)&p_z, g_z);
    cudaGetSymbolAddress((void**)&p_z1, g_z1);
    cudaGetSymbolAddress((void**)&p_z2, g_z2);

    const int TB = 256;

    // layer 1 (NF=64 -> 32)
    k_agg1_init<<<(NN * NFD + TB - 1) / TB, TB>>>(x);
    k_agg1_edges<<<(int)(((long)NE * 2 * 32 + TB - 1) / TB), TB>>>(x, ei);
    k_mlp1<<<1184, TB>>>(w1a, b1a, ws_b, bs_b);
    k_bnfin<<<1, 32>>>(bn_g, bn_b);

    // layers 2-5 (32 -> 32)
    for (int i = 0; i < 4; i++) {
        k_agg_init<<<(NN * DD + TB - 1) / TB, TB>>>();
        k_agg_edges<<<(int)(((long)NE * 32 + TB - 1) / TB), TB>>>(ei);
        k_mlp<<<1184, TB>>>(ws_a + i * DD * DD, bs_a + i * DD,
                            ws_b + (i + 1) * DD * DD, bs_b + (i + 1) * DD);
        k_bnfin<<<1, 32>>>(bn_g + (i + 1) * DD, bn_b + (i + 1) * DD);
    }

    // pool
    k_pool_zero<<<(NG * DD + TB - 1) / TB, TB>>>();
    k_pool<<<(NN * DD + TB - 1) / TB, TB>>>(batch);

    // head
    k_gemm<<<dim3(128 / 64, NG / 64), 256>>>(p_pooled, fcg_w, fcg_b, p_z,
                                             NG, DD, 128, 256, 1);
    k_gemm<<<dim3(256 / 64, NG / 64), 256>>>(sf, fs1_w, fs1_b, p_s1,
                                             NG, 512, 256, 256, 1);
    k_gemm<<<dim3(128 / 64, NG / 64), 256>>>(p_s1, fs2_w, fs2_b, p_z + 128,
                                             NG, 256, 128, 256, 1);
    k_gemm<<<dim3(1024 / 64, NG / 64), 256>>>(p_z, fc1_w, fc1_b, p_z1,
                                              NG, 256, 1024, 1024, 1);
    k_gemm<<<dim3(256 / 64, NG / 64), 256>>>(p_z1, fc2_w, fc2_b, p_z2,
                                             NG, 1024, 256, 256, 1);
    k_out<<<(NG * 32 + TB - 1) / TB, TB>>>(out_w, out_b, out);
}

// round 4
// speedup vs baseline: 1.8605x; 1.8605x over previous
#include <cuda_runtime.h>
#include <cuda_bf16.h>

#define NN 100000     // nodes
#define NE 1600000    // edges
#define NG 2048       // graphs
#define NFD 64        // node feature dim
#define DD 32         // hidden dim
#define BN_EPS 1e-5f
#define SCAN_B 512
#define NSB 196       // ceil(NN/SCAN_B)
#define NWB 1184      // blocks for layer kernels (8 warps each)

// ---------------- scratch ----------------
__device__ int    g_rowptr[NN + 1];
__device__ int    g_rowcur[NN];        // histogram counts, then scatter cursors
__device__ int    g_csrc[NE];          // CSR: src node ids grouped by dst
__device__ int    g_bsum[256];
__device__ float  g_ta[NN * DD];
__device__ float  g_tb[NN * DD];
__device__ double g_stats[5 * 64];     // per layer: [sum(32) | sumsq(32)]
__device__ float  g_pooled[NG * DD];
__device__ float  g_s1[NG * 256];
__device__ float  g_z[NG * 256];
__device__ float  g_z1[NG * 1024];
__device__ float  g_z2[NG * 256];

// ---------------- CSR build ----------------
__global__ void k_init() {
    int i = blockIdx.x * blockDim.x + threadIdx.x;
    if (i < NN) g_rowcur[i] = 0;
    if (i < 5 * 64) g_stats[i] = 0.0;
    if (i < NG * DD) g_pooled[i] = 0.f;
}

__global__ void k_hist(const int* __restrict__ ei) {
    int t = blockIdx.x * blockDim.x + threadIdx.x;
    if (t < NE) atomicAdd(&g_rowcur[ei[NE + t]], 1);
}

__global__ void k_scan1() {
    __shared__ int sh[SCAN_B];
    int t = threadIdx.x, b = blockIdx.x;
    int i = b * SCAN_B + t;
    int v = (i < NN) ? g_rowcur[i] : 0;
    sh[t] = v; __syncthreads();
    for (int off = 1; off < SCAN_B; off <<= 1) {
        int a = (t >= off) ? sh[t - off] : 0;
        __syncthreads();
        sh[t] += a;
        __syncthreads();
    }
    if (i < NN) g_rowptr[i] = sh[t] - v;
    if (t == SCAN_B - 1) g_bsum[b] = sh[t];
}

__global__ void k_scan2() {
    __shared__ int sh[256];
    int t = threadIdx.x;
    int v = (t < NSB) ? g_bsum[t] : 0;
    sh[t] = v; __syncthreads();
    for (int off = 1; off < 256; off <<= 1) {
        int a = (t >= off) ? sh[t - off] : 0;
        __syncthreads();
        sh[t] += a;
        __syncthreads();
    }
    if (t < NSB) g_bsum[t] = sh[t] - v;
}

__global__ void k_scan3() {
    int i = blockIdx.x * blockDim.x + threadIdx.x;
    if (i < NN) {
        int rp = g_rowptr[i] + g_bsum[i >> 9];
        g_rowptr[i] = rp;
        g_rowcur[i] = rp;
    }
    if (i == 0) g_rowptr[NN] = NE;
}

__global__ void k_scatter(const int* __restrict__ ei) {
    int t = blockIdx.x * blockDim.x + threadIdx.x;
    if (t >= NE) return;
    int d = ei[NE + t];
    int pos = atomicAdd(&g_rowcur[d], 1);
    g_csrc[pos] = ei[t];
}

// ---------------- layer 1: gather(x) + MLP(64->32->32) + BN stats ----------------
__global__ void k_layer1(const float* __restrict__ x,
                         const float* __restrict__ wa, const float* __restrict__ ba,
                         const float* __restrict__ wb, const float* __restrict__ bb) {
    __shared__ float swa[NFD * DD];
    __shared__ float swb[DD * DD];
    __shared__ float sba[DD], sbb[DD];
    __shared__ double rsum[8][DD], rsq[8][DD];
    int tid = threadIdx.x;
    for (int i = tid; i < NFD * DD; i += blockDim.x) swa[i] = wa[i];
    for (int i = tid; i < DD * DD; i += blockDim.x)  swb[i] = wb[i];
    if (tid < DD) { sba[tid] = ba[tid]; sbb[tid] = bb[tid]; }
    __syncthreads();

    int lane = tid & 31, wid = tid >> 5;
    int warp   = (blockIdx.x * blockDim.x + tid) >> 5;
    int nwarps = (gridDim.x * blockDim.x) >> 5;
    float ssum = 0.f, ssq = 0.f;

    for (int r = warp; r < NN; r += nwarps) {
        float a0 = x[r * NFD + lane];
        float a1 = x[r * NFD + 32 + lane];
        int start = g_rowptr[r], end = g_rowptr[r + 1];
        for (int e = start; e < end; e += 32) {
            int nrem = end - e;
            int cnt = nrem < 32 ? nrem : 32;
            int s_l = (lane < cnt) ? g_csrc[e + lane] : 0;
            int j = 0;
            for (; j + 4 <= cnt; j += 4) {
                int s0 = __shfl_sync(0xffffffffu, s_l, j);
                int s1 = __shfl_sync(0xffffffffu, s_l, j + 1);
                int s2 = __shfl_sync(0xffffffffu, s_l, j + 2);
                int s3 = __shfl_sync(0xffffffffu, s_l, j + 3);
                float u0 = x[s0 * NFD + lane],      v0 = x[s0 * NFD + 32 + lane];
                float u1 = x[s1 * NFD + lane],      v1 = x[s1 * NFD + 32 + lane];
                float u2 = x[s2 * NFD + lane],      v2 = x[s2 * NFD + 32 + lane];
                float u3 = x[s3 * NFD + lane],      v3 = x[s3 * NFD + 32 + lane];
                a0 += (u0 + u1) + (u2 + u3);
                a1 += (v0 + v1) + (v2 + v3);
            }
            for (; j < cnt; j++) {
                int s = __shfl_sync(0xffffffffu, s_l, j);
                a0 += x[s * NFD + lane];
                a1 += x[s * NFD + 32 + lane];
            }
        }
        float h = sba[lane];
        #pragma unroll
        for (int k = 0; k < 32; k++)
            h = fmaf(__shfl_sync(0xffffffffu, a0, k), swa[k * DD + lane], h);
        #pragma unroll
        for (int k = 0; k < 32; k++)
            h = fmaf(__shfl_sync(0xffffffffu, a1, k), swa[(k + 32) * DD + lane], h);
        h = fmaxf(h, 0.f);
        float o = sbb[lane];
        #pragma unroll
        for (int k = 0; k < 32; k++)
            o = fmaf(__shfl_sync(0xffffffffu, h, k), swb[k * DD + lane], o);
        g_ta[r * DD + lane] = o;
        ssum += o;
        ssq = fmaf(o, o, ssq);
    }
    rsum[wid][lane] = (double)ssum;
    rsq[wid][lane]  = (double)ssq;
    __syncthreads();
    if (wid == 0) {
        double a = 0.0, b = 0.0;
        #pragma unroll
        for (int w = 0; w < 8; w++) { a += rsum[w][lane]; b += rsq[w][lane]; }
        atomicAdd(&g_stats[lane], a);
        atomicAdd(&g_stats[32 + lane], b);
    }
}

// ---------------- layers 2-5: BN-relu(tin) gather + MLP + stats ----------------
__global__ void k_layer(const float* __restrict__ tin, float* __restrict__ tout,
                        const float* __restrict__ wa, const float* __restrict__ ba,
                        const float* __restrict__ wb, const float* __restrict__ bb,
                        const float* __restrict__ bng, const float* __restrict__ bnb,
                        const double* __restrict__ stats_in, double* __restrict__ stats_out) {
    __shared__ float swa[DD * DD];
    __shared__ float swb[DD * DD];
    __shared__ float sba[DD], sbb[DD], ssc[DD], ssh[DD];
    __shared__ double rsum[8][DD], rsq[8][DD];
    int tid = threadIdx.x;
    for (int i = tid; i < DD * DD; i += blockDim.x) { swa[i] = wa[i]; swb[i] = wb[i]; }
    if (tid < DD) {
        sba[tid] = ba[tid]; sbb[tid] = bb[tid];
        double mu  = stats_in[tid] / (double)NN;
        double var = stats_in[32 + tid] / (double)NN - mu * mu;
        float sc = bng[tid] * rsqrtf((float)var + BN_EPS);
        ssc[tid] = sc;
        ssh[tid] = bnb[tid] - (float)mu * sc;
    }
    __syncthreads();

    int lane = tid & 31, wid = tid >> 5;
    int warp   = (blockIdx.x * blockDim.x + tid) >> 5;
    int nwarps = (gridDim.x * blockDim.x) >> 5;
    float sc = ssc[lane], sh = ssh[lane];
    float ssum = 0.f, ssq = 0.f;

    for (int r = warp; r < NN; r += nwarps) {
        float a = fmaxf(fmaf(tin[r * DD + lane], sc, sh), 0.f);
        int start = g_rowptr[r], end = g_rowptr[r + 1];
        for (int e = start; e < end; e += 32) {
            int nrem = end - e;
            int cnt = nrem < 32 ? nrem : 32;
            int s_l = (lane < cnt) ? g_csrc[e + lane] : 0;
            int j = 0;
            for (; j + 4 <= cnt; j += 4) {
                int s0 = __shfl_sync(0xffffffffu, s_l, j);
                int s1 = __shfl_sync(0xffffffffu, s_l, j + 1);
                int s2 = __shfl_sync(0xffffffffu, s_l, j + 2);
                int s3 = __shfl_sync(0xffffffffu, s_l, j + 3);
                float v0 = fmaxf(fmaf(tin[s0 * DD + lane], sc, sh), 0.f);
                float v1 = fmaxf(fmaf(tin[s1 * DD + lane], sc, sh), 0.f);
                float v2 = fmaxf(fmaf(tin[s2 * DD + lane], sc, sh), 0.f);
                float v3 = fmaxf(fmaf(tin[s3 * DD + lane], sc, sh), 0.f);
                a += (v0 + v1) + (v2 + v3);
            }
            for (; j < cnt; j++) {
                int s = __shfl_sync(0xffffffffu, s_l, j);
                a += fmaxf(fmaf(tin[s * DD + lane], sc, sh), 0.f);
            }
        }
        float h = sba[lane];
        #pragma unroll
        for (int k = 0; k < 32; k++)
            h = fmaf(__shfl_sync(0xffffffffu, a, k), swa[k * DD + lane], h);
        h = fmaxf(h, 0.f);
        float o = sbb[lane];
        #pragma unroll
        for (int k = 0; k < 32; k++)
            o = fmaf(__shfl_sync(0xffffffffu, h, k), swb[k * DD + lane], o);
        tout[r * DD + lane] = o;
        ssum += o;
        ssq = fmaf(o, o, ssq);
    }
    rsum[wid][lane] = (double)ssum;
    rsq[wid][lane]  = (double)ssq;
    __syncthreads();
    if (wid == 0) {
        double a = 0.0, b = 0.0;
        #pragma unroll
        for (int w = 0; w < 8; w++) { a += rsum[w][lane]; b += rsq[w][lane]; }
        atomicAdd(&stats_out[lane], a);
        atomicAdd(&stats_out[32 + lane], b);
    }
}

// ---------------- pooling (applies last BN on the fly) ----------------
__global__ void k_pool(const int* __restrict__ batch,
                       const float* __restrict__ tin,
                       const float* __restrict__ bng, const float* __restrict__ bnb,
                       const double* __restrict__ stats_in) {
    __shared__ float ssc[DD], ssh[DD];
    int tid = threadIdx.x;
    if (tid < DD) {
        double mu  = stats_in[tid] / (double)NN;
        double var = stats_in[32 + tid] / (double)NN - mu * mu;
        float sc = bng[tid] * rsqrtf((float)var + BN_EPS);
        ssc[tid] = sc;
        ssh[tid] = bnb[tid] - (float)mu * sc;
    }
    __syncthreads();
    int idx = blockIdx.x * blockDim.x + tid;
    if (idx >= NN * DD) return;
    int i = idx >> 5, f = idx & 31;
    float v = fmaxf(fmaf(tin[idx], ssc[f], ssh[f]), 0.f);
    atomicAdd(&g_pooled[batch[i] * DD + f], v);
}

// ---------------- head GEMM ----------------
__global__ void k_gemm(const float* __restrict__ A, const float* __restrict__ W,
                       const float* __restrict__ bias, float* __restrict__ C,
                       int M, int K, int Nc, int ldc, int do_relu) {
    const int BM = 64, BN = 64, BK = 16;
    __shared__ float As[BK][BM + 1];
    __shared__ float Ws[BK][BN];
    int tx = threadIdx.x & 15, ty = threadIdx.x >> 4;
    int row0 = blockIdx.y * BM, col0 = blockIdx.x * BN;
    float acc[4][4] = {};
    for (int k0 = 0; k0 < K; k0 += BK) {
        for (int i = threadIdx.x; i < BM * BK; i += 256) {
            int m = i >> 4, kk = i & 15;
            As[kk][m] = A[(long)(row0 + m) * K + k0 + kk];
        }
        for (int i = threadIdx.x; i < BK * BN; i += 256) {
            int kk = i >> 6, n = i & 63;
            Ws[kk][n] = W[(long)(k0 + kk) * Nc + col0 + n];
        }
        __syncthreads();
        #pragma unroll
        for (int kk = 0; kk < BK; kk++) {
            float a[4], w[4];
            #pragma unroll
            for (int i = 0; i < 4; i++) a[i] = As[kk][ty * 4 + i];
            #pragma unroll
            for (int j = 0; j < 4; j++) w[j] = Ws[kk][tx * 4 + j];
            #pragma unroll
            for (int i = 0; i < 4; i++)
                #pragma unroll
                for (int j = 0; j < 4; j++) acc[i][j] = fmaf(a[i], w[j], acc[i][j]);
        }
        __syncthreads();
    }
    #pragma unroll
    for (int i = 0; i < 4; i++) {
        int r = row0 + ty * 4 + i;
        #pragma unroll
        for (int j = 0; j < 4; j++) {
            int c = col0 + tx * 4 + j;
            float v = acc[i][j] + bias[c];
            if (do_relu) v = fmaxf(v, 0.f);
            C[(long)r * ldc + c] = v;
        }
    }
}

__global__ void k_out(const float* __restrict__ ow, const float* __restrict__ ob,
                      float* __restrict__ out) {
    int warp = (blockIdx.x * blockDim.x + threadIdx.x) >> 5;
    int lane = threadIdx.x & 31;
    if (warp >= NG) return;
    float acc = 0.f;
    #pragma unroll
    for (int k = lane; k < 256; k += 32)
        acc = fmaf(g_z2[warp * 256 + k], ow[k], acc);
    #pragma unroll
    for (int o = 16; o; o >>= 1) acc += __shfl_down_sync(0xffffffffu, acc, o);
    if (lane == 0) out[warp] = acc + ob[0];
}

// ---------------- launch ----------------
extern "C" void kernel_launch(void* const* d_in, const int* in_sizes, int n_in,
                              void* d_out, int out_size) {
    const float* x     = (const float*)d_in[0];
    const int*   ei    = (const int*)d_in[1];
    const int*   batch = (const int*)d_in[2];
    const float* sf    = (const float*)d_in[3];
    const float* w1a   = (const float*)d_in[4];
    const float* b1a   = (const float*)d_in[5];
    const float* ws_a  = (const float*)d_in[6];
    const float* bs_a  = (const float*)d_in[7];
    const float* ws_b  = (const float*)d_in[8];
    const float* bs_b  = (const float*)d_in[9];
    const float* bn_g  = (const float*)d_in[10];
    const float* bn_b  = (const float*)d_in[11];
    const float* fcg_w = (const float*)d_in[12];
    const float* fcg_b = (const float*)d_in[13];
    const float* fs1_w = (const float*)d_in[14];
    const float* fs1_b = (const float*)d_in[15];
    const float* fs2_w = (const float*)d_in[16];
    const float* fs2_b = (const float*)d_in[17];
    const float* fc1_w = (const float*)d_in[18];
    const float* fc1_b = (const float*)d_in[19];
    const float* fc2_w = (const float*)d_in[20];
    const float* fc2_b = (const float*)d_in[21];
    const float* out_w = (const float*)d_in[22];
    const float* out_b = (const float*)d_in[23];
    float* out = (float*)d_out;

    float *p_ta, *p_tb, *p_pooled, *p_s1, *p_z, *p_z1, *p_z2;
    double* p_stats;
    cudaGetSymbolAddress((void**)&p_ta, g_ta);
    cudaGetSymbolAddress((void**)&p_tb, g_tb);
    cudaGetSymbolAddress((void**)&p_stats, g_stats);
    cudaGetSymbolAddress((void**)&p_pooled, g_pooled);
    cudaGetSymbolAddress((void**)&p_s1, g_s1);
    cudaGetSymbolAddress((void**)&p_z, g_z);
    cudaGetSymbolAddress((void**)&p_z1, g_z1);
    cudaGetSymbolAddress((void**)&p_z2, g_z2);

    const int TB = 256;

    // CSR build (keyed by dst)
    k_init<<<(NN + TB - 1) / TB, TB>>>();
    k_hist<<<(NE + TB - 1) / TB, TB>>>(ei);
    k_scan1<<<NSB, SCAN_B>>>();
    k_scan2<<<1, 256>>>();
    k_scan3<<<(NN + TB - 1) / TB, TB>>>();
    k_scatter<<<(NE + TB - 1) / TB, TB>>>(ei);

    // layer 1 (x -> g_ta), stats[0]
    k_layer1<<<NWB, TB>>>(x, w1a, b1a, ws_b, bs_b);

    // layers 2-5, ping-pong ta/tb
    float* bufs[2] = { p_ta, p_tb };
    for (int i = 1; i < 5; i++) {
        k_layer<<<NWB, TB>>>(bufs[(i + 1) & 1], bufs[i & 1],
                             ws_a + (i - 1) * DD * DD, bs_a + (i - 1) * DD,
                             ws_b + i * DD * DD, bs_b + i * DD,
                             bn_g + (i - 1) * DD, bn_b + (i - 1) * DD,
                             p_stats + (i - 1) * 64, p_stats + i * 64);
    }
    // after loop: layer 5 output in bufs[5&1] = g_tb? i=4 -> tout=bufs[0]=p_ta
    float* last = bufs[4 & 1];  // p_ta

    // pool with BN of layer 5 (stats[4])
    k_pool<<<(NN * DD + TB - 1) / TB, TB>>>(batch, last,
                                            bn_g + 4 * DD, bn_b + 4 * DD,
                                            p_stats + 4 * 64);

    // head
    k_gemm<<<dim3(128 / 64, NG / 64), 256>>>(p_pooled, fcg_w, fcg_b, p_z,
                                             NG, DD, 128, 256, 1);
    k_gemm<<<dim3(256 / 64, NG / 64), 256>>>(sf, fs1_w, fs1_b, p_s1,
                                             NG, 512, 256, 256, 1);
    k_gemm<<<dim3(128 / 64, NG / 64), 256>>>(p_s1, fs2_w, fs2_b, p_z + 128,
                                             NG, 256, 128, 256, 1);
    k_gemm<<<dim3(1024 / 64, NG / 64), 256>>>(p_z, fc1_w, fc1_b, p_z1,
                                              NG, 256, 1024, 1024, 1);
    k_gemm<<<dim3(256 / 64, NG / 64), 256>>>(p_z1, fc2_w, fc2_b, p_z2,
                                             NG, 1024, 256, 256, 1);
    k_out<<<(NG * 32 + TB - 1) / TB, TB>>>(out_w, out_b, out);
}